// round 1
// baseline (speedup 1.0000x reference)
#include <cuda_runtime.h>
#include <cuda_bf16.h>
#include <mma.h>
#include <cstdint>

using namespace nvcuda;

// Problem dims (fixed by the dataset)
#define T_STEPS 256
#define BATCH   128
#define N_INP   784
#define N_HID   512
#define N_OUT   128
#define M_TOTAL (T_STEPS * BATCH)   // 32768

// ---------------------------------------------------------------------------
// Scratch (static device globals -- the sanctioned alloc-free scratch path)
// ---------------------------------------------------------------------------
__device__ __align__(128) signed char g_wh_l0[N_HID * N_INP];
__device__ __align__(128) signed char g_wh_l1[N_HID * N_INP];
__device__ __align__(128) signed char g_wh_l2[N_HID * N_INP];
__device__ __align__(128) signed char g_wo_l0[N_OUT * N_HID];
__device__ __align__(128) signed char g_wo_l1[N_OUT * N_HID];
__device__ __align__(128) signed char g_wo_l2[N_OUT * N_HID];
__device__ __align__(128) float       g_ch[M_TOTAL * N_HID];   // 64 MB
__device__ __align__(128) signed char g_sh[M_TOTAL * N_HID];   // 16 MB
__device__ __align__(128) float       g_co[M_TOTAL * N_OUT];   // 16 MB

// ---------------------------------------------------------------------------
// Weight -> 3x signed-int8 limb decomposition (exact: w_q = (l2<<16|l1<<8|l0)*2^-22)
// Quantization err <= 2^-23 absolute ~ fp32 ulp on these weights (|w| < ~2).
// ---------------------------------------------------------------------------
__global__ void prep_limbs_kernel(const float* __restrict__ w,
                                  signed char* __restrict__ l0,
                                  signed char* __restrict__ l1,
                                  signed char* __restrict__ l2,
                                  int n)
{
    int idx = blockIdx.x * blockDim.x + threadIdx.x;
    if (idx >= n) return;
    float s = w[idx] * 4194304.0f;                       // 2^22
    s = fminf(fmaxf(s, -8323072.0f), 8323072.0f);        // keep limbs in range
    int q  = __float2int_rn(s);
    int b0 = (int)(signed char)(q & 0xFF);  q = (q - b0) >> 8;
    int b1 = (int)(signed char)(q & 0xFF);  q = (q - b1) >> 8;
    l0[idx] = (signed char)b0;
    l1[idx] = (signed char)b1;
    l2[idx] = (signed char)q;                            // |q| <= 127 by clamp
}

// ---------------------------------------------------------------------------
// Limb GEMM: C[M,N] = (A[M,K] . B[N,K]^T) reconstructed to fp32.
// A is binary (0/1): fp32 spikes (converted inline) or s8 hidden spikes.
// B given as 3 limb planes. BM=128, BN=64, BK=16, 256 threads, 8 warps (4x2),
// warp tile 32x32 via 2x2 m16n16k16 s8 fragments, 3 int accumulators per tile.
// ---------------------------------------------------------------------------
#define BM 128
#define BN 64
#define BK 16

template<int KTOT, bool AF32>
__global__ __launch_bounds__(256)
void gemm_limb_kernel(const void* __restrict__ Araw,
                      const signed char* __restrict__ B0,
                      const signed char* __restrict__ B1,
                      const signed char* __restrict__ B2,
                      float* __restrict__ C, int NTOT)
{
    // Rows padded to 32B stride so wmma fragment pointers are 32B-aligned.
    __shared__ __align__(128) uint32_t As4[BM][8];      // valid cols 0..3 (16 s8/row)
    __shared__ __align__(128) uint32_t Bs4[3][BN][8];   // valid cols 0..3

    const int tid    = threadIdx.x;
    const int wid    = tid >> 5;
    const int warp_m = wid & 3;    // 0..3  (32 rows each)
    const int warp_n = wid >> 2;   // 0..1  (32 cols each)
    const int m0     = blockIdx.y * BM;
    const int n0     = blockIdx.x * BN;

    wmma::fragment<wmma::accumulator, 16, 16, 16, int> acc[3][2][2];
#pragma unroll
    for (int l = 0; l < 3; l++)
#pragma unroll
        for (int i = 0; i < 2; i++)
#pragma unroll
            for (int j = 0; j < 2; j++)
                wmma::fill_fragment(acc[l][i][j], 0);

    const signed char* Bp[3] = {B0, B1, B2};

    for (int k0 = 0; k0 < KTOT; k0 += BK) {
        // ---- load A tile (128 x 16 s8) ----
        if constexpr (AF32) {
            const float* A = (const float*)Araw;
#pragma unroll
            for (int s = 0; s < 2; s++) {
                int slot = tid + s * 256;           // 0..511
                int row  = slot >> 2;
                int c4   = slot & 3;
                float4 f = *(const float4*)(A + (size_t)(m0 + row) * KTOT + k0 + c4 * 4);
                uint32_t p = (f.x > 0.5f ? 1u : 0u)
                           | ((f.y > 0.5f ? 1u : 0u) << 8)
                           | ((f.z > 0.5f ? 1u : 0u) << 16)
                           | ((f.w > 0.5f ? 1u : 0u) << 24);
                As4[row][c4] = p;
            }
        } else {
            const uint32_t* A = (const uint32_t*)Araw;
#pragma unroll
            for (int s = 0; s < 2; s++) {
                int slot = tid + s * 256;
                int row  = slot >> 2;
                int c4   = slot & 3;
                As4[row][c4] = A[(size_t)(m0 + row) * (KTOT / 4) + (k0 >> 2) + c4];
            }
        }
        // ---- load B limb tiles (3 x 64 x 16 s8) ----
#pragma unroll
        for (int s = 0; s < 3; s++) {
            int slot = tid + s * 256;               // 0..767
            int l    = slot >> 8;
            int r    = slot & 255;
            int row  = r >> 2;
            int c4   = r & 3;
            Bs4[l][row][c4] =
                *(const uint32_t*)(Bp[l] + (size_t)(n0 + row) * KTOT + k0 + c4 * 4);
        }
        __syncthreads();

        wmma::fragment<wmma::matrix_a, 16, 16, 16, signed char, wmma::row_major> af[2];
        wmma::fragment<wmma::matrix_b, 16, 16, 16, signed char, wmma::col_major> bf[3][2];
#pragma unroll
        for (int i = 0; i < 2; i++)
            wmma::load_matrix_sync(af[i],
                (const signed char*)&As4[warp_m * 32 + i * 16][0], 32);
#pragma unroll
        for (int l = 0; l < 3; l++)
#pragma unroll
            for (int j = 0; j < 2; j++)
                wmma::load_matrix_sync(bf[l][j],
                    (const signed char*)&Bs4[l][warp_n * 32 + j * 16][0], 32);
#pragma unroll
        for (int l = 0; l < 3; l++)
#pragma unroll
            for (int i = 0; i < 2; i++)
#pragma unroll
                for (int j = 0; j < 2; j++)
                    wmma::mma_sync(acc[l][i][j], af[i], bf[l][j], acc[l][i][j]);
        __syncthreads();
    }

    // ---- epilogue: combine limbs -> fp32, scale by 2^-22 ----
    const float S = 1.0f / 4194304.0f;
#pragma unroll
    for (int i = 0; i < 2; i++)
#pragma unroll
        for (int j = 0; j < 2; j++) {
            wmma::fragment<wmma::accumulator, 16, 16, 16, float> f;
#pragma unroll
            for (int e = 0; e < f.num_elements; e++)
                f.x[e] = ((float)acc[2][i][j].x[e] * 65536.0f
                        + (float)acc[1][i][j].x[e] * 256.0f
                        + (float)acc[0][i][j].x[e]) * S;
            wmma::store_matrix_sync(
                C + (size_t)(m0 + warp_m * 32 + i * 16) * NTOT + n0 + warp_n * 32 + j * 16,
                f, NTOT, wmma::mem_row_major);
        }
}

// ---------------------------------------------------------------------------
// CUBA LIF scan over time. One thread per (b, h). Matches reference op order:
//   v += A*(i - v);  i = i*Cdec + x;  z = (v - 1) > 0;  v = z ? 0 : v
// ---------------------------------------------------------------------------
__global__ void lif_kernel(const float* __restrict__ ch, signed char* __restrict__ sh)
{
    const int tid = blockIdx.x * blockDim.x + threadIdx.x;   // b*512 + h
    const float Am = (float)(1e-6 * (1.0 / 6e-6));           // 0.16666667f
    const float Cd = (float)(1.0 - 1e-6 * (1.0 / 6e-6));     // 0.83333334f
    float v = 0.0f, cur = 0.0f;
    const int stride = BATCH * N_HID;                         // 65536

    for (int t0 = 0; t0 < T_STEPS; t0 += 8) {
        float x[8];
#pragma unroll
        for (int u = 0; u < 8; u++)
            x[u] = ch[(size_t)(t0 + u) * stride + tid];
#pragma unroll
        for (int u = 0; u < 8; u++) {
            v = v + Am * (cur - v);
            cur = cur * Cd + x[u];
            bool z = (v - 1.0f) > 0.0f;
            sh[(size_t)(t0 + u) * stride + tid] = (signed char)(z ? 1 : 0);
            if (z) v = 0.0f;
        }
    }
}

// ---------------------------------------------------------------------------
// CUBA LI (readout) scan. One thread per (b, o). Emits post-update membrane.
// ---------------------------------------------------------------------------
__global__ void li_kernel(const float* __restrict__ co, float* __restrict__ out)
{
    const int tid = blockIdx.x * blockDim.x + threadIdx.x;   // b*128 + o
    const float Am = (float)(1e-6 * (1.0 / 6e-6));
    const float Cd = (float)(1.0 - 1e-6 * (1.0 / 6e-6));
    float v = 0.0f, cur = 0.0f;
    const int stride = BATCH * N_OUT;                         // 16384

    for (int t0 = 0; t0 < T_STEPS; t0 += 8) {
        float x[8];
#pragma unroll
        for (int u = 0; u < 8; u++)
            x[u] = co[(size_t)(t0 + u) * stride + tid];
#pragma unroll
        for (int u = 0; u < 8; u++) {
            v = v + Am * (cur - v);
            cur = cur * Cd + x[u];
            out[(size_t)(t0 + u) * stride + tid] = v;
        }
    }
}

// ---------------------------------------------------------------------------
// Launch: prep limbs -> GEMM1 -> LIF -> GEMM2 -> LI  (default stream, capturable)
// ---------------------------------------------------------------------------
extern "C" void kernel_launch(void* const* d_in, const int* in_sizes, int n_in,
                              void* d_out, int out_size)
{
    const float* spikes = (const float*)d_in[0];   // [256,128,784] f32 (binary)
    const float* wh     = (const float*)d_in[1];   // [512,784] f32
    const float* wo     = (const float*)d_in[2];   // [128,512] f32
    float*       out    = (float*)d_out;           // [256,128,128] f32

    signed char *wh0, *wh1, *wh2, *wo0, *wo1, *wo2, *sh;
    float *ch, *co;
    cudaGetSymbolAddress((void**)&wh0, g_wh_l0);
    cudaGetSymbolAddress((void**)&wh1, g_wh_l1);
    cudaGetSymbolAddress((void**)&wh2, g_wh_l2);
    cudaGetSymbolAddress((void**)&wo0, g_wo_l0);
    cudaGetSymbolAddress((void**)&wo1, g_wo_l1);
    cudaGetSymbolAddress((void**)&wo2, g_wo_l2);
    cudaGetSymbolAddress((void**)&ch,  g_ch);
    cudaGetSymbolAddress((void**)&sh,  g_sh);
    cudaGetSymbolAddress((void**)&co,  g_co);

    // 1) weight limb decomposition (cheap, deterministic, every call)
    prep_limbs_kernel<<<(N_HID * N_INP + 255) / 256, 256>>>(wh, wh0, wh1, wh2, N_HID * N_INP);
    prep_limbs_kernel<<<(N_OUT * N_HID + 255) / 256, 256>>>(wo, wo0, wo1, wo2, N_OUT * N_HID);

    // 2) c_h = spikes @ w_hidden^T   [32768 x 512]
    {
        dim3 grid(N_HID / BN, M_TOTAL / BM);   // x = n-block first => A tiles reuse L2
        gemm_limb_kernel<N_INP, true><<<grid, 256>>>(spikes, wh0, wh1, wh2, ch, N_HID);
    }

    // 3) LIF scan -> binary hidden spikes (s8)
    lif_kernel<<<(BATCH * N_HID) / 256, 256>>>(ch, sh);

    // 4) c_o = s_h @ w_out^T   [32768 x 128]
    {
        dim3 grid(N_OUT / BN, M_TOTAL / BM);
        gemm_limb_kernel<N_HID, false><<<grid, 256>>>(sh, wo0, wo1, wo2, co, N_OUT);
    }

    // 5) LI readout scan -> output membrane trace
    li_kernel<<<(BATCH * N_OUT) / 256, 256>>>(co, out);
}